// round 1
// baseline (speedup 1.0000x reference)
#include <cuda_runtime.h>

#define NN 100000
#define EE 3200000
#define GG 1024
#define DD 32
#define SCAN_T 1024
#define CHUNK ((NN + SCAN_T - 1) / SCAN_T)   // 98

// ---- scratch (static __device__, no allocations) ----
__device__ int   g_deg[NN];
__device__ int   g_off[NN];
__device__ int   g_cur[NN];
__device__ int   g_csr[EE];
__device__ float g_h0[NN * DD];
__device__ float g_h1[NN * DD];
__device__ float g_pool[GG * DD];

// ---------------- CSR build ----------------
__global__ void k_zero_deg() {
    int i = blockIdx.x * blockDim.x + threadIdx.x;
    if (i < NN) g_deg[i] = 0;
}

__global__ void k_zero_pool() {
    int i = blockIdx.x * blockDim.x + threadIdx.x;
    if (i < GG * DD) g_pool[i] = 0.f;
}

__global__ void k_hist(const int* __restrict__ ei) {
    int e = blockIdx.x * blockDim.x + threadIdx.x;
    if (e < EE) atomicAdd(&g_deg[ei[EE + e]], 1);
}

__global__ void k_scan() {
    __shared__ int sh[SCAN_T];
    int t = threadIdx.x;
    int start = t * CHUNK;
    int end = min(start + CHUNK, NN);
    int s = 0;
    for (int i = start; i < end; i++) s += g_deg[i];
    sh[t] = s;
    __syncthreads();
    // Kogge-Stone inclusive scan
    for (int off = 1; off < SCAN_T; off <<= 1) {
        int v = (t >= off) ? sh[t - off] : 0;
        __syncthreads();
        sh[t] += v;
        __syncthreads();
    }
    int run = (t == 0) ? 0 : sh[t - 1];
    for (int i = start; i < end; i++) {
        g_off[i] = run;
        g_cur[i] = run;
        run += g_deg[i];
    }
}

__global__ void k_fill(const int* __restrict__ ei) {
    int e = blockIdx.x * blockDim.x + threadIdx.x;
    if (e < EE) {
        int dst = ei[EE + e];
        int p = atomicAdd(&g_cur[dst], 1);
        g_csr[p] = ei[e];
    }
}

// ---------------- layer 1 (F_IN=3 -> 32) ----------------
__global__ void k_layer1(const float* __restrict__ x,
                         const float* __restrict__ Wa, const float* __restrict__ ba,
                         const float* __restrict__ Wb, const float* __restrict__ bb,
                         const float* __restrict__ gm, const float* __restrict__ be,
                         const float* __restrict__ mm, const float* __restrict__ vv) {
    __shared__ float sWa[96], sWb[1024], sba[32], sbb[32], ssc[32], ssh[32];
    int tid = threadIdx.x;
    for (int i = tid; i < 1024; i += blockDim.x) sWb[i] = Wb[i];
    if (tid < 96) sWa[tid] = Wa[tid];
    if (tid < 32) {
        sba[tid] = ba[tid];
        sbb[tid] = bb[tid];
        float sc = gm[tid] * rsqrtf(vv[tid] + 1e-5f);
        ssc[tid] = sc;
        ssh[tid] = be[tid] - mm[tid] * sc;
    }
    __syncthreads();
    int warp = (blockIdx.x * blockDim.x + tid) >> 5;
    int lane = tid & 31;
    if (warp >= NN) return;
    int n = warp;
    int o = g_off[n], d = g_deg[n];
    float p0 = 0.f, p1 = 0.f, p2 = 0.f;
    for (int j = lane; j < d; j += 32) {
        int ss = g_csr[o + j];
        const float* xp = x + 3 * ss;
        p0 += xp[0];
        p1 += xp[1];
        p2 += xp[2];
    }
#pragma unroll
    for (int w = 16; w > 0; w >>= 1) {
        p0 += __shfl_xor_sync(0xffffffffu, p0, w);
        p1 += __shfl_xor_sync(0xffffffffu, p1, w);
        p2 += __shfl_xor_sync(0xffffffffu, p2, w);
    }
    float a0 = p0 + x[3 * n];
    float a1 = p1 + x[3 * n + 1];
    float a2 = p2 + x[3 * n + 2];
    float acc = fmaf(a0, sWa[lane], sba[lane]);
    acc = fmaf(a1, sWa[32 + lane], acc);
    acc = fmaf(a2, sWa[64 + lane], acc);
    acc = fmaxf(acc, 0.f);
    float acc2 = sbb[lane];
#pragma unroll
    for (int k = 0; k < 32; k++) {
        float a = __shfl_sync(0xffffffffu, acc, k);
        acc2 = fmaf(a, sWb[k * 32 + lane], acc2);
    }
    acc2 = fmaxf(acc2, 0.f);
    g_h0[n * 32 + lane] = fmaf(acc2, ssc[lane], ssh[lane]);
}

// ---------------- layers 2/3 (32 -> 32) ----------------
// dir==0: g_h0 -> g_h1 ; dir==1: g_h1 -> g_h0
__global__ void k_layer32(int dir,
                          const float* __restrict__ Wa, const float* __restrict__ ba,
                          const float* __restrict__ Wb, const float* __restrict__ bb,
                          const float* __restrict__ gm, const float* __restrict__ be,
                          const float* __restrict__ mm, const float* __restrict__ vv) {
    __shared__ float sWa[1024], sWb[1024], sba[32], sbb[32], ssc[32], ssh[32];
    int tid = threadIdx.x;
    for (int i = tid; i < 1024; i += blockDim.x) {
        sWa[i] = Wa[i];
        sWb[i] = Wb[i];
    }
    if (tid < 32) {
        sba[tid] = ba[tid];
        sbb[tid] = bb[tid];
        float sc = gm[tid] * rsqrtf(vv[tid] + 1e-5f);
        ssc[tid] = sc;
        ssh[tid] = be[tid] - mm[tid] * sc;
    }
    __syncthreads();
    const float* __restrict__ hin = dir ? g_h1 : g_h0;
    float* __restrict__ hout = dir ? g_h0 : g_h1;
    int warp = (blockIdx.x * blockDim.x + tid) >> 5;
    int lane = tid & 31;
    if (warp >= NN) return;
    int n = warp;
    float agg = hin[n * 32 + lane];
    int o = g_off[n];
    int jend = o + g_deg[n];
#pragma unroll 4
    for (int j = o; j < jend; j++) {
        int ss = g_csr[j];              // lane-uniform load, L1-resident line
        agg += hin[ss * 32 + lane];     // coalesced 128B row gather (L2-resident)
    }
    float acc = sba[lane];
#pragma unroll
    for (int k = 0; k < 32; k++) {
        float a = __shfl_sync(0xffffffffu, agg, k);
        acc = fmaf(a, sWa[k * 32 + lane], acc);
    }
    acc = fmaxf(acc, 0.f);
    float acc2 = sbb[lane];
#pragma unroll
    for (int k = 0; k < 32; k++) {
        float a = __shfl_sync(0xffffffffu, acc, k);
        acc2 = fmaf(a, sWb[k * 32 + lane], acc2);
    }
    acc2 = fmaxf(acc2, 0.f);
    hout[n * 32 + lane] = fmaf(acc2, ssc[lane], ssh[lane]);
}

// ---------------- global add pool ----------------
__global__ void k_pool(const int* __restrict__ batch) {
    int i = blockIdx.x * blockDim.x + threadIdx.x;
    if (i < NN * DD) {
        int n = i >> 5;
        int f = i & 31;
        atomicAdd(&g_pool[batch[n] * 32 + f], g_h0[i]);
    }
}

// ---------------- head MLP ----------------
__global__ void k_final(const float* __restrict__ Wf1, const float* __restrict__ bf1,
                        const float* __restrict__ Wf2, const float* __restrict__ bf2,
                        float* __restrict__ out) {
    __shared__ float sW1[1024], sb1[32], sW2[32];
    int tid = threadIdx.x;
    for (int i = tid; i < 1024; i += blockDim.x) sW1[i] = Wf1[i];
    if (tid < 32) {
        sb1[tid] = bf1[tid];
        sW2[tid] = Wf2[tid];
    }
    __syncthreads();
    int warp = (blockIdx.x * blockDim.x + tid) >> 5;
    int lane = tid & 31;
    if (warp >= GG) return;
    float p = g_pool[warp * 32 + lane];
    float acc = sb1[lane];
#pragma unroll
    for (int k = 0; k < 32; k++) {
        float a = __shfl_sync(0xffffffffu, p, k);
        acc = fmaf(a, sW1[k * 32 + lane], acc);
    }
    acc = fmaxf(acc, 0.f);
    float part = acc * sW2[lane];
#pragma unroll
    for (int w = 16; w > 0; w >>= 1) part += __shfl_xor_sync(0xffffffffu, part, w);
    if (lane == 0) out[warp] = tanhf(part + bf2[0]);
}

extern "C" void kernel_launch(void* const* d_in, const int* in_sizes, int n_in,
                              void* d_out, int out_size) {
    const float* x = (const float*)d_in[0];
    const int* ei = (const int*)d_in[1];
    const int* batch = (const int*)d_in[2];
    const float* P[28];
    for (int i = 0; i < 28; i++) P[i] = (const float*)d_in[3 + i];
    float* out = (float*)d_out;

    const int TB = 256;
    // CSR build (by dst)
    k_zero_deg<<<(NN + TB - 1) / TB, TB>>>();
    k_hist<<<(EE + TB - 1) / TB, TB>>>(ei);
    k_scan<<<1, SCAN_T>>>();
    k_fill<<<(EE + TB - 1) / TB, TB>>>(ei);

    int node_grid = (NN * 32 + TB - 1) / TB;   // warp per node
    // layer 1: x -> g_h0
    k_layer1<<<node_grid, TB>>>(x, P[0], P[1], P[2], P[3], P[4], P[5], P[6], P[7]);
    // layer 2: g_h0 -> g_h1
    k_layer32<<<node_grid, TB>>>(0, P[8], P[9], P[10], P[11], P[12], P[13], P[14], P[15]);
    // layer 3: g_h1 -> g_h0
    k_layer32<<<node_grid, TB>>>(1, P[16], P[17], P[18], P[19], P[20], P[21], P[22], P[23]);

    // pool + head
    k_zero_pool<<<(GG * DD + TB - 1) / TB, TB>>>();
    k_pool<<<(NN * DD + TB - 1) / TB, TB>>>(batch);
    k_final<<<(GG * DD + TB - 1) / TB, TB>>>(P[24], P[25], P[26], P[27], out);
}

// round 3
// speedup vs baseline: 1.6025x; 1.6025x over previous
#include <cuda_runtime.h>

#define NN 100000
#define EE 3200000
#define GG 1024
#define DD 32
#define TILE 1024
#define NTILES ((NN + TILE - 1) / TILE)   // 98

// ---- scratch (static __device__, no allocations) ----
__device__ int    g_deg[NN];
__device__ int    g_off[NN];
__device__ int    g_cur[NN];
__device__ int    g_csr[EE];
__device__ int    g_bsum[128];
__device__ float4 g_x4[NN];
__device__ float  g_h0[NN * DD];
__device__ float  g_h1[NN * DD];
__device__ float  g_pool[GG * DD];

// ---------------- init: zero deg + pool, pad x to float4 ----------------
__global__ void k_init(const float* __restrict__ x) {
    int i = blockIdx.x * blockDim.x + threadIdx.x;
    if (i < NN) {
        g_deg[i] = 0;
        g_x4[i] = make_float4(x[3 * i], x[3 * i + 1], x[3 * i + 2], 0.f);
    }
    if (i < GG * DD) g_pool[i] = 0.f;
}

// ---------------- CSR build ----------------
__global__ void k_hist(const int* __restrict__ ei) {
    int e = blockIdx.x * blockDim.x + threadIdx.x;
    if (e < EE) atomicAdd(&g_deg[ei[EE + e]], 1);
}

__global__ void k_scan1() {
    __shared__ int sh[TILE];
    int t = threadIdx.x;
    int idx = blockIdx.x * TILE + t;
    int v = (idx < NN) ? g_deg[idx] : 0;
    sh[t] = v;
    __syncthreads();
    for (int off = 1; off < TILE; off <<= 1) {
        int u = (t >= off) ? sh[t - off] : 0;
        __syncthreads();
        sh[t] += u;
        __syncthreads();
    }
    if (idx < NN) g_off[idx] = sh[t] - v;          // tile-local exclusive
    if (t == TILE - 1) g_bsum[blockIdx.x] = sh[t]; // tile total
}

__global__ void k_scan2() {
    __shared__ int sh[128];
    int t = threadIdx.x;
    int v = (t < NTILES) ? g_bsum[t] : 0;
    sh[t] = v;
    __syncthreads();
    for (int off = 1; off < 128; off <<= 1) {
        int u = (t >= off) ? sh[t - off] : 0;
        __syncthreads();
        sh[t] += u;
        __syncthreads();
    }
    if (t < NTILES) g_bsum[t] = sh[t] - v;         // exclusive tile offsets
}

__global__ void k_scan3() {
    int idx = blockIdx.x * TILE + threadIdx.x;
    if (idx < NN) {
        int o = g_off[idx] + g_bsum[blockIdx.x];
        g_off[idx] = o;
        g_cur[idx] = o;
    }
}

__global__ void k_fill(const int* __restrict__ ei) {
    int e = blockIdx.x * blockDim.x + threadIdx.x;
    if (e < EE) {
        int dst = ei[EE + e];
        int p = atomicAdd(&g_cur[dst], 1);
        g_csr[p] = ei[e];
    }
}

// ---------------- layer 1 (F_IN=3 -> 32) ----------------
__global__ void k_layer1(const float* __restrict__ Wa, const float* __restrict__ ba,
                         const float* __restrict__ Wb, const float* __restrict__ bb,
                         const float* __restrict__ gm, const float* __restrict__ be,
                         const float* __restrict__ mm, const float* __restrict__ vv) {
    __shared__ float sWa[96], sWb[1024], sba[32], sbb[32], ssc[32], ssh[32];
    int tid = threadIdx.x;
    for (int i = tid; i < 1024; i += blockDim.x) sWb[i] = Wb[i];
    if (tid < 96) sWa[tid] = Wa[tid];
    if (tid < 32) {
        sba[tid] = ba[tid];
        sbb[tid] = bb[tid];
        float sc = gm[tid] * rsqrtf(vv[tid] + 1e-5f);
        ssc[tid] = sc;
        ssh[tid] = be[tid] - mm[tid] * sc;
    }
    __syncthreads();
    int warp = (blockIdx.x * blockDim.x + tid) >> 5;
    int lane = tid & 31;
    if (warp >= NN) return;
    int n = warp;
    int o = g_off[n], d = g_deg[n];
    float p0 = 0.f, p1 = 0.f, p2 = 0.f;
    for (int j = lane; j < d; j += 32) {
        float4 r = g_x4[g_csr[o + j]];
        p0 += r.x; p1 += r.y; p2 += r.z;
    }
#pragma unroll
    for (int w = 16; w > 0; w >>= 1) {
        p0 += __shfl_xor_sync(0xffffffffu, p0, w);
        p1 += __shfl_xor_sync(0xffffffffu, p1, w);
        p2 += __shfl_xor_sync(0xffffffffu, p2, w);
    }
    float4 self = g_x4[n];
    float a0 = p0 + self.x, a1 = p1 + self.y, a2 = p2 + self.z;
    float acc = fmaf(a0, sWa[lane], sba[lane]);
    acc = fmaf(a1, sWa[32 + lane], acc);
    acc = fmaf(a2, sWa[64 + lane], acc);
    acc = fmaxf(acc, 0.f);
    float acc2 = sbb[lane];
#pragma unroll
    for (int k = 0; k < 32; k++) {
        float a = __shfl_sync(0xffffffffu, acc, k);
        acc2 = fmaf(a, sWb[k * 32 + lane], acc2);
    }
    acc2 = fmaxf(acc2, 0.f);
    g_h0[n * 32 + lane] = fmaf(acc2, ssc[lane], ssh[lane]);
}

// ---------------- layers 2/3 (32 -> 32), float4 gather, 4 edges/warp-iter ----------------
// dir==0: g_h0 -> g_h1 ; dir==1: g_h1 -> g_h0
__global__ void k_layer32(int dir,
                          const float* __restrict__ Wa, const float* __restrict__ ba,
                          const float* __restrict__ Wb, const float* __restrict__ bb,
                          const float* __restrict__ gm, const float* __restrict__ be,
                          const float* __restrict__ mm, const float* __restrict__ vv) {
    __shared__ float sWa[1024], sWb[1024], sba[32], sbb[32], ssc[32], ssh[32];
    int tid = threadIdx.x;
    for (int i = tid; i < 1024; i += blockDim.x) {
        sWa[i] = Wa[i];
        sWb[i] = Wb[i];
    }
    if (tid < 32) {
        sba[tid] = ba[tid];
        sbb[tid] = bb[tid];
        float sc = gm[tid] * rsqrtf(vv[tid] + 1e-5f);
        ssc[tid] = sc;
        ssh[tid] = be[tid] - mm[tid] * sc;
    }
    __syncthreads();
    const float4* __restrict__ hin4 = (const float4*)(dir ? g_h1 : g_h0);
    float* __restrict__ hout = dir ? g_h0 : g_h1;
    int warp = (blockIdx.x * blockDim.x + tid) >> 5;
    int lane = tid & 31;
    if (warp >= NN) return;
    int n = warp;
    int grp = lane >> 3;     // edge group 0..3
    int chk = lane & 7;      // float4 chunk 0..7 of the 32-float row
    // self term counted once (group 0 only)
    float4 acc4 = (grp == 0) ? hin4[n * 8 + chk] : make_float4(0.f, 0.f, 0.f, 0.f);
    int o = g_off[n];
    int jend = o + g_deg[n];
#pragma unroll 4
    for (int j = o + grp; j < jend; j += 4) {
        int ss = g_csr[j];                 // 4 ints per warp, 8-way broadcast
        float4 r = hin4[ss * 8 + chk];     // 4 coalesced 128B rows per warp-iter
        acc4.x += r.x; acc4.y += r.y; acc4.z += r.z; acc4.w += r.w;
    }
    // reduce the 4 edge groups
#pragma unroll
    for (int w = 8; w <= 16; w <<= 1) {
        acc4.x += __shfl_xor_sync(0xffffffffu, acc4.x, w);
        acc4.y += __shfl_xor_sync(0xffffffffu, acc4.y, w);
        acc4.z += __shfl_xor_sync(0xffffffffu, acc4.z, w);
        acc4.w += __shfl_xor_sync(0xffffffffu, acc4.w, w);
    }
    // MLP a: feature k lives in component (k&3) of lanes with chk == k>>2
    float acc = sba[lane];
#pragma unroll
    for (int k = 0; k < 32; k++) {
        float comp = ((k & 3) == 0) ? acc4.x :
                     ((k & 3) == 1) ? acc4.y :
                     ((k & 3) == 2) ? acc4.z : acc4.w;
        float a = __shfl_sync(0xffffffffu, comp, k >> 2);
        acc = fmaf(a, sWa[k * 32 + lane], acc);
    }
    acc = fmaxf(acc, 0.f);
    float acc2 = sbb[lane];
#pragma unroll
    for (int k = 0; k < 32; k++) {
        float a = __shfl_sync(0xffffffffu, acc, k);
        acc2 = fmaf(a, sWb[k * 32 + lane], acc2);
    }
    acc2 = fmaxf(acc2, 0.f);
    hout[n * 32 + lane] = fmaf(acc2, ssc[lane], ssh[lane]);
}

// ---------------- global add pool (batch is sorted -> run-length accumulate) ----------------
__global__ void k_pool(const int* __restrict__ batch) {
    int warp = (blockIdx.x * blockDim.x + threadIdx.x) >> 5;
    int lane = threadIdx.x & 31;
    int base = warp * 32;
    if (base >= NN) return;
    int end = min(base + 32, NN);
    float acc = 0.f;
    int curb = batch[base];
    for (int n = base; n < end; n++) {
        int b = batch[n];
        if (b != curb) {
            atomicAdd(&g_pool[curb * 32 + lane], acc);
            acc = 0.f;
            curb = b;
        }
        acc += g_h0[n * 32 + lane];
    }
    atomicAdd(&g_pool[curb * 32 + lane], acc);
}

// ---------------- head MLP ----------------
__global__ void k_final(const float* __restrict__ Wf1, const float* __restrict__ bf1,
                        const float* __restrict__ Wf2, const float* __restrict__ bf2,
                        float* __restrict__ out) {
    __shared__ float sW1[1024], sb1[32], sW2[32];
    int tid = threadIdx.x;
    for (int i = tid; i < 1024; i += blockDim.x) sW1[i] = Wf1[i];
    if (tid < 32) {
        sb1[tid] = bf1[tid];
        sW2[tid] = Wf2[tid];
    }
    __syncthreads();
    int warp = (blockIdx.x * blockDim.x + tid) >> 5;
    int lane = tid & 31;
    if (warp >= GG) return;
    float p = g_pool[warp * 32 + lane];
    float acc = sb1[lane];
#pragma unroll
    for (int k = 0; k < 32; k++) {
        float a = __shfl_sync(0xffffffffu, p, k);
        acc = fmaf(a, sW1[k * 32 + lane], acc);
    }
    acc = fmaxf(acc, 0.f);
    float part = acc * sW2[lane];
#pragma unroll
    for (int w = 16; w > 0; w >>= 1) part += __shfl_xor_sync(0xffffffffu, part, w);
    if (lane == 0) out[warp] = tanhf(part + bf2[0]);
}

extern "C" void kernel_launch(void* const* d_in, const int* in_sizes, int n_in,
                              void* d_out, int out_size) {
    const float* x = (const float*)d_in[0];
    const int* ei = (const int*)d_in[1];
    const int* batch = (const int*)d_in[2];
    const float* P[28];
    for (int i = 0; i < 28; i++) P[i] = (const float*)d_in[3 + i];
    float* out = (float*)d_out;

    const int TB = 256;
    // init + CSR build (by dst)
    k_init<<<(NN + TB - 1) / TB, TB>>>(x);
    k_hist<<<(EE + TB - 1) / TB, TB>>>(ei);
    k_scan1<<<NTILES, TILE>>>();
    k_scan2<<<1, 128>>>();
    k_scan3<<<NTILES, TILE>>>();
    k_fill<<<(EE + TB - 1) / TB, TB>>>(ei);

    int node_grid = (NN * 32 + TB - 1) / TB;   // warp per node
    // layer 1: x -> g_h0
    k_layer1<<<node_grid, TB>>>(P[0], P[1], P[2], P[3], P[4], P[5], P[6], P[7]);
    // layer 2: g_h0 -> g_h1
    k_layer32<<<node_grid, TB>>>(0, P[8], P[9], P[10], P[11], P[12], P[13], P[14], P[15]);
    // layer 3: g_h1 -> g_h0
    k_layer32<<<node_grid, TB>>>(1, P[16], P[17], P[18], P[19], P[20], P[21], P[22], P[23]);

    // pool + head
    k_pool<<<(NN + TB - 1) / TB * 32 / 32, TB>>>(batch);
    k_final<<<(GG * DD + TB - 1) / TB, TB>>>(P[24], P[25], P[26], P[27], out);
}